// round 2
// baseline (speedup 1.0000x reference)
#include <cuda_runtime.h>

#define BSZ 128
#define SEQ 2048
#define NV 64
#define DM 512
#define KC 64
#define NPTS (BSZ*NV)            /* 8192 */
#define PROB_SIZE (NPTS*KC)      /* 524288 */
#define CENT_SIZE (KC*DM)        /* 32768 */
#define XEMB_OFF (PROB_SIZE+CENT_SIZE) /* 557056 */
#define MAX_ITER 10
#define NCHUNK 64                /* point chunks for segment-sum partials */

__device__ float g_cent[CENT_SIZE];
__device__ float g_cent_new[CENT_SIZE];
__device__ float g_csq[KC];
__device__ float g_xsq[NPTS];
__device__ int   g_ids[NPTS];
__device__ float g_shift[KC];
__device__ float g_part[NCHUNK*CENT_SIZE];  /* 8 MB */
__device__ int   g_pcnt[NCHUNK*KC];
__device__ int   g_done;

/* ---------- packed fp32x2 helpers (Blackwell) ---------- */
static __device__ __forceinline__ unsigned long long pk2(float lo, float hi){
    unsigned long long r;
    asm("mov.b64 %0, {%1, %2};" : "=l"(r)
        : "r"(__float_as_uint(lo)), "r"(__float_as_uint(hi)));
    return r;
}
static __device__ __forceinline__ unsigned long long fma2(unsigned long long a,
                                                          unsigned long long b,
                                                          unsigned long long c){
    unsigned long long d;
    asm("fma.rn.f32x2 %0, %1, %2, %3;" : "=l"(d) : "l"(a), "l"(b), "l"(c));
    return d;
}
static __device__ __forceinline__ void upk2(unsigned long long v, float &lo, float &hi){
    unsigned int a, b;
    asm("mov.b64 {%0, %1}, %2;" : "=r"(a), "=r"(b) : "l"(v));
    lo = __uint_as_float(a); hi = __uint_as_float(b);
}

/* ---------- init: copy centroids, clear done ---------- */
__global__ void init_kernel(const float* __restrict__ cents){
    int i = blockIdx.x * blockDim.x + threadIdx.x;
    if (i < CENT_SIZE) g_cent[i] = cents[i];
    if (i == 0) g_done = 0;
}

/* ---------- main GEMM: x_emb[n,d] = sum_s x[b,s,v]*W[d,s] + b[d] ----------
   128(M) x 128(N) x 16(K) tiles, 256 threads, 8x8 microtile via fma.rn.f32x2.
   A element (n, s) lives at x[(n>>6)*SEQ*NV + s*NV + (n&63)] (v contiguous). */
__global__ void __launch_bounds__(256) gemm_kernel(const float* __restrict__ x,
                                                   const float* __restrict__ W,
                                                   const float* __restrict__ bias,
                                                   float* __restrict__ xemb){
    __shared__ float As[16][128];
    __shared__ float Bs[16][128];
    const int tid = threadIdx.x;
    const int d0 = blockIdx.x * 128;   /* output-dim tile */
    const int n0 = blockIdx.y * 128;   /* point tile      */

    /* per-thread load mapping: 2 float4 for A, 2 float4 for B per k-tile */
    int a_m[2], a_c[2], a_base[2];
    int b_d[2], b_s4[2], b_base[2];
#pragma unroll
    for (int j = 0; j < 2; j++){
        int q = j*256 + tid;            /* 0..511 */
        a_m[j] = (q & 31) * 4;          /* m row 0..124 */
        a_c[j] = q >> 5;                /* k col 0..15  */
        int gn = n0 + a_m[j];
        a_base[j] = (gn >> 6) * (SEQ*NV) + (gn & 63);
        b_d[j]  = q >> 2;               /* 0..127 */
        b_s4[j] = (q & 3) * 4;          /* 0,4,8,12 */
        b_base[j] = (d0 + b_d[j]) * SEQ + b_s4[j];
    }

    unsigned long long acc[8][4];
#pragma unroll
    for (int m = 0; m < 8; m++)
#pragma unroll
        for (int j = 0; j < 4; j++) acc[m][j] = 0ull;

    const int tr = tid >> 4, tc = tid & 15;
    const int mb = tr * 8, nb = tc * 8;

    float4 ra[2], rb[2];
#pragma unroll
    for (int j = 0; j < 2; j++){
        ra[j] = *(const float4*)(x + a_base[j] + a_c[j]*NV);
        rb[j] = *(const float4*)(W + b_base[j]);
    }

    const int NT = SEQ / 16;
    for (int t = 0; t < NT; t++){
        __syncthreads();
#pragma unroll
        for (int j = 0; j < 2; j++){
            *(float4*)&As[a_c[j]][a_m[j]] = ra[j];
            Bs[b_s4[j]+0][b_d[j]] = rb[j].x;
            Bs[b_s4[j]+1][b_d[j]] = rb[j].y;
            Bs[b_s4[j]+2][b_d[j]] = rb[j].z;
            Bs[b_s4[j]+3][b_d[j]] = rb[j].w;
        }
        __syncthreads();
        if (t + 1 < NT){
            int s0 = (t + 1) * 16;
#pragma unroll
            for (int j = 0; j < 2; j++){
                ra[j] = *(const float4*)(x + a_base[j] + (s0 + a_c[j])*NV);
                rb[j] = *(const float4*)(W + b_base[j] + s0);
            }
        }
#pragma unroll
        for (int k = 0; k < 16; k++){
            float4 a0 = *(const float4*)&As[k][mb];
            float4 a1 = *(const float4*)&As[k][mb+4];
            float4 b0 = *(const float4*)&Bs[k][nb];
            float4 b1 = *(const float4*)&Bs[k][nb+4];
            unsigned long long bp[4];
            bp[0] = pk2(b0.x, b0.y); bp[1] = pk2(b0.z, b0.w);
            bp[2] = pk2(b1.x, b1.y); bp[3] = pk2(b1.z, b1.w);
            float am8[8] = {a0.x,a0.y,a0.z,a0.w,a1.x,a1.y,a1.z,a1.w};
#pragma unroll
            for (int m = 0; m < 8; m++){
                unsigned long long a2 = pk2(am8[m], am8[m]);
#pragma unroll
                for (int j = 0; j < 4; j++)
                    acc[m][j] = fma2(a2, bp[j], acc[m][j]);
            }
        }
    }

    /* epilogue: add bias, write x_emb */
#pragma unroll
    for (int m = 0; m < 8; m++){
        int gn = n0 + mb + m;
        float o[8];
#pragma unroll
        for (int j = 0; j < 4; j++) upk2(acc[m][j], o[2*j], o[2*j+1]);
#pragma unroll
        for (int j = 0; j < 8; j++) o[j] += bias[d0 + nb + j];
        float* orow = xemb + gn*DM + d0 + nb;
        *(float4*)orow      = make_float4(o[0],o[1],o[2],o[3]);
        *(float4*)(orow+4)  = make_float4(o[4],o[5],o[6],o[7]);
    }
}

/* ---------- x_sq[n] = sum_d x_emb[n,d]^2 (one warp per row) ---------- */
__global__ void xsq_kernel(const float* __restrict__ xemb){
    int w = threadIdx.x >> 5, lane = threadIdx.x & 31;
    int row = blockIdx.x * 8 + w;
    float a = 0.f;
#pragma unroll
    for (int j = 0; j < 4; j++){
        float4 v = *(const float4*)(xemb + row*DM + j*128 + lane*4);
        a += v.x*v.x + v.y*v.y + v.z*v.z + v.w*v.w;
    }
#pragma unroll
    for (int off = 16; off > 0; off >>= 1) a += __shfl_down_sync(0xffffffffu, a, off);
    if (lane == 0) g_xsq[row] = a;
}

/* ---------- c_sq[k] = sum_d cent[k,d]^2 ---------- */
__global__ void csq_kernel(){
    __shared__ float red[128];
    int k = blockIdx.x, t = threadIdx.x;
    float a = 0.f;
    for (int i = t; i < DM; i += 128){ float v = g_cent[k*DM + i]; a = fmaf(v, v, a); }
    red[t] = a; __syncthreads();
    for (int s = 64; s > 0; s >>= 1){ if (t < s) red[t] += red[t+s]; __syncthreads(); }
    if (t == 0) g_csq[k] = red[0];
}

/* ---------- assign: argmin_k (x_sq - 2 x.c + c_sq), first-index ties ----------
   256 threads = 64 points x 4 centroid-groups of 16. */
__global__ void __launch_bounds__(256) assign_kernel(const float* __restrict__ xemb){
    if (g_done) return;
    __shared__ float xs[64][68];
    __shared__ float cs[64][64];
    __shared__ float bv[4][64];
    __shared__ int   bi[4][64];
    const int tid = threadIdx.x;
    const int pl = tid & 63;
    const int g  = tid >> 6;
    const int p  = blockIdx.x * 64 + pl;

    float acc[16];
#pragma unroll
    for (int i = 0; i < 16; i++) acc[i] = 0.f;

    for (int d0 = 0; d0 < DM; d0 += 64){
#pragma unroll
        for (int j = 0; j < 4; j++){
            int q = j*256 + tid;         /* 0..1023 */
            int r = q >> 4;              /* 0..63   */
            int c4 = (q & 15) * 4;       /* 0..60   */
            float4 v = *(const float4*)(xemb + (blockIdx.x*64 + r)*DM + d0 + c4);
            *(float4*)&xs[r][c4] = v;
            float4 w = *(const float4*)(&g_cent[r*DM + d0 + c4]);
            *(float4*)&cs[r][c4] = w;
        }
        __syncthreads();
#pragma unroll
        for (int dd = 0; dd < 64; dd += 8){
            float4 x0 = *(const float4*)&xs[pl][dd];
            float4 x1 = *(const float4*)&xs[pl][dd+4];
#pragma unroll
            for (int kk = 0; kk < 16; kk++){
                const float* cp = &cs[g*16 + kk][dd];
                float4 c0 = *(const float4*)cp;
                float4 c1 = *(const float4*)(cp + 4);
                float a = acc[kk];
                a = fmaf(x0.x, c0.x, a); a = fmaf(x0.y, c0.y, a);
                a = fmaf(x0.z, c0.z, a); a = fmaf(x0.w, c0.w, a);
                a = fmaf(x1.x, c1.x, a); a = fmaf(x1.y, c1.y, a);
                a = fmaf(x1.z, c1.z, a); a = fmaf(x1.w, c1.w, a);
                acc[kk] = a;
            }
        }
        __syncthreads();
    }

    float xq = g_xsq[p];
    float best = 3.4e38f;
    int bk = 0;
#pragma unroll
    for (int kk = 0; kk < 16; kk++){
        int k = g*16 + kk;
        float d2 = (xq - 2.0f*acc[kk]) + g_csq[k];
        if (d2 < best){ best = d2; bk = k; }
    }
    bv[g][pl] = best; bi[g][pl] = bk;
    __syncthreads();
    if (g == 0){
#pragma unroll
        for (int gg = 1; gg < 4; gg++){
            float v = bv[gg][pl];
            if (v < best){ best = v; bk = bi[gg][pl]; }
        }
        g_ids[p] = bk;
    }
}

/* ---------- segment-sum partials: grid (4 dim-groups, 64 point-chunks) ----------
   Deterministic: points processed in ascending n within a chunk. */
__global__ void __launch_bounds__(128) partial_kernel(const float* __restrict__ xemb){
    if (g_done) return;
    __shared__ float sums[KC*128];
    __shared__ int sids[128];
    __shared__ int scnt[KC];
    const int tid = threadIdx.x;
    const int dg = blockIdx.x;       /* 0..3  */
    const int ch = blockIdx.y;       /* 0..63 */
    for (int i = tid; i < KC*128; i += 128) sums[i] = 0.f;
    if (tid < KC) scnt[tid] = 0;
    sids[tid] = g_ids[ch*128 + tid];
    __syncthreads();
    const int dbase = dg * 128;
    for (int p = 0; p < 128; p++){
        int id = sids[p];
        sums[id*128 + tid] += xemb[(ch*128 + p)*DM + dbase + tid];
        if (dg == 0 && tid == 0) scnt[id]++;
    }
    __syncthreads();
    for (int i = tid; i < KC*128; i += 128){
        int k = i >> 7, dd = i & 127;
        g_part[ch*CENT_SIZE + k*DM + dbase + dd] = sums[i];
    }
    if (dg == 0 && tid < KC) g_pcnt[ch*KC + tid] = scnt[tid];
}

/* ---------- combine partials -> new centroids + per-cluster shift ---------- */
__global__ void __launch_bounds__(512) combine_kernel(){
    if (g_done) return;
    __shared__ float red[512];
    const int k = blockIdx.x, d = threadIdx.x;
    float acc = 0.f;
    for (int b = 0; b < NCHUNK; b++) acc += g_part[b*CENT_SIZE + k*DM + d];
    int cnt = 0;
    for (int b = 0; b < NCHUNK; b++) cnt += g_pcnt[b*KC + k];
    float old = g_cent[k*DM + d];
    float nc = (cnt > 0) ? (acc / (float)cnt) : old;
    g_cent_new[k*DM + d] = nc;
    float df = nc - old;
    red[d] = df * df;
    __syncthreads();
    for (int s = 256; s > 0; s >>= 1){ if (d < s) red[d] += red[d+s]; __syncthreads(); }
    if (d == 0) g_shift[k] = red[0];
}

/* ---------- finalize: apply update, set done if ||shift|| < TOL ---------- */
__global__ void finalize_kernel(){
    if (g_done) return;
    const int tid = threadIdx.x;
    for (int i = tid; i < CENT_SIZE; i += 256) g_cent[i] = g_cent_new[i];
    if (tid == 0){
        float s = 0.f;
        for (int k = 0; k < KC; k++) s += g_shift[k];
        if (s < 1e-8f) g_done = 1;   /* norm < 1e-4 <=> sumsq < 1e-8 */
    }
}

/* ---------- outputs: one-hot prob + centroid copy ---------- */
__global__ void output_kernel(float* __restrict__ out){
    int i = blockIdx.x * blockDim.x + threadIdx.x;
    if (i < PROB_SIZE){
        out[i] = (g_ids[i >> 6] == (i & 63)) ? 1.0f : 0.0f;
    } else if (i < PROB_SIZE + CENT_SIZE){
        out[i] = g_cent[i - PROB_SIZE];
    }
}

extern "C" void kernel_launch(void* const* d_in, const int* in_sizes, int n_in,
                              void* d_out, int out_size){
    const float* x     = (const float*)d_in[0];   /* [128,2048,64] */
    const float* W     = (const float*)d_in[1];   /* [512,2048]    */
    const float* bias  = (const float*)d_in[2];   /* [512]         */
    const float* cents = (const float*)d_in[3];   /* [64,512]      */
    float* out  = (float*)d_out;
    float* xemb = out + XEMB_OFF;

    init_kernel<<<(CENT_SIZE + 255)/256, 256>>>(cents);
    gemm_kernel<<<dim3(DM/128, NPTS/128), 256>>>(x, W, bias, xemb);
    xsq_kernel<<<NPTS/8, 256>>>(xemb);

    for (int it = 0; it < MAX_ITER; it++){
        csq_kernel<<<KC, 128>>>();
        assign_kernel<<<NPTS/64, 256>>>(xemb);
        partial_kernel<<<dim3(4, NCHUNK), 128>>>(xemb);
        combine_kernel<<<KC, 512>>>();
        finalize_kernel<<<1, 256>>>();
    }
    output_kernel<<<(PROB_SIZE + CENT_SIZE + 255)/256, 256>>>(out);
}

// round 3
// speedup vs baseline: 1.2600x; 1.2600x over previous
#include <cuda_runtime.h>

#define BSZ 128
#define SEQ 2048
#define NV 64
#define DM 512
#define KC 64
#define NPTS (BSZ*NV)            /* 8192 */
#define PROB_SIZE (NPTS*KC)      /* 524288 */
#define CENT_SIZE (KC*DM)        /* 32768 */
#define XEMB_OFF (PROB_SIZE+CENT_SIZE) /* 557056 */
#define MAX_ITER 10
#define NCHUNK 64                /* point chunks for segment-sum partials */

typedef unsigned long long ull;

__device__ float g_cent[CENT_SIZE];
__device__ float g_csq[KC];
__device__ float g_xsq[NPTS];
__device__ int   g_ids[NPTS];
__device__ float g_shift[KC];
__device__ float g_part[NCHUNK*CENT_SIZE];  /* 8 MB */
__device__ int   g_pcnt[NCHUNK*KC];
__device__ int   g_done;
__device__ int   g_ctr[MAX_ITER];

/* ---------- packed fp32x2 helpers (Blackwell) ---------- */
static __device__ __forceinline__ ull pk2(float lo, float hi){
    ull r;
    asm("mov.b64 %0, {%1, %2};" : "=l"(r)
        : "r"(__float_as_uint(lo)), "r"(__float_as_uint(hi)));
    return r;
}
static __device__ __forceinline__ ull fma2(ull a, ull b, ull c){
    ull d;
    asm("fma.rn.f32x2 %0, %1, %2, %3;" : "=l"(d) : "l"(a), "l"(b), "l"(c));
    return d;
}
static __device__ __forceinline__ void upk2(ull v, float &lo, float &hi){
    unsigned int a, b;
    asm("mov.b64 {%0, %1}, %2;" : "=r"(a), "=r"(b) : "l"(v));
    lo = __uint_as_float(a); hi = __uint_as_float(b);
}

/* ---------- init: copy centroids, clear done + counters ---------- */
__global__ void init_kernel(const float* __restrict__ cents){
    int i = blockIdx.x * blockDim.x + threadIdx.x;
    if (i < CENT_SIZE) g_cent[i] = cents[i];
    if (i == 0) g_done = 0;
    if (i < MAX_ITER) g_ctr[i] = 0;
}

/* ---------- main GEMM: x_emb[n,d] = sum_s x[b,s,v]*W[d,s] + b[d] ----------
   128(M) x 128(N) x 16(K) tiles, 256 threads. Accumulators are m-pair-packed
   f32x2 so A pairs come straight out of LDS.128; only B needs dup movs. */
__global__ void __launch_bounds__(256,2) gemm_kernel(const float* __restrict__ x,
                                                     const float* __restrict__ W,
                                                     const float* __restrict__ bias,
                                                     float* __restrict__ xemb){
    __shared__ __align__(16) float As[16][128];
    __shared__ __align__(16) float Bs[16][128];
    const int tid = threadIdx.x;
    const int d0 = blockIdx.x * 128;   /* output-dim tile */
    const int n0 = blockIdx.y * 128;   /* point tile      */

    int a_m[2], a_c[2], a_base[2];
    int b_d[2], b_s4[2], b_base[2];
#pragma unroll
    for (int j = 0; j < 2; j++){
        int q = j*256 + tid;            /* 0..511 */
        a_m[j] = (q & 31) * 4;          /* m row 0..124 */
        a_c[j] = q >> 5;                /* k col 0..15  */
        int gn = n0 + a_m[j];
        a_base[j] = (gn >> 6) * (SEQ*NV) + (gn & 63);
        b_d[j]  = q >> 2;               /* 0..127 */
        b_s4[j] = (q & 3) * 4;          /* 0,4,8,12 */
        b_base[j] = (d0 + b_d[j]) * SEQ + b_s4[j];
    }

    ull acc[4][8];                      /* [m-pair][n] */
#pragma unroll
    for (int m = 0; m < 4; m++)
#pragma unroll
        for (int j = 0; j < 8; j++) acc[m][j] = 0ull;

    const int tr = tid >> 4, tc = tid & 15;
    const int mb = tr * 8, nb = tc * 8;

    float4 ra[2], rb[2];
#pragma unroll
    for (int j = 0; j < 2; j++){
        ra[j] = *(const float4*)(x + a_base[j] + a_c[j]*NV);
        rb[j] = *(const float4*)(W + b_base[j]);
    }

    const int NT = SEQ / 16;
    for (int t = 0; t < NT; t++){
        __syncthreads();
#pragma unroll
        for (int j = 0; j < 2; j++){
            *(float4*)&As[a_c[j]][a_m[j]] = ra[j];
            Bs[b_s4[j]+0][b_d[j]] = rb[j].x;
            Bs[b_s4[j]+1][b_d[j]] = rb[j].y;
            Bs[b_s4[j]+2][b_d[j]] = rb[j].z;
            Bs[b_s4[j]+3][b_d[j]] = rb[j].w;
        }
        __syncthreads();
        if (t + 1 < NT){
            int s0 = (t + 1) * 16;
#pragma unroll
            for (int j = 0; j < 2; j++){
                ra[j] = *(const float4*)(x + a_base[j] + (s0 + a_c[j])*NV);
                rb[j] = *(const float4*)(W + b_base[j] + s0);
            }
        }
#pragma unroll
        for (int k = 0; k < 16; k++){
            ulonglong2 A0 = *(const ulonglong2*)&As[k][mb];
            ulonglong2 A1 = *(const ulonglong2*)&As[k][mb+4];
            ull am[4] = {A0.x, A0.y, A1.x, A1.y};
            float4 b0 = *(const float4*)&Bs[k][nb];
            float4 b1 = *(const float4*)&Bs[k][nb+4];
            ull bb[8];
            bb[0] = pk2(b0.x, b0.x); bb[1] = pk2(b0.y, b0.y);
            bb[2] = pk2(b0.z, b0.z); bb[3] = pk2(b0.w, b0.w);
            bb[4] = pk2(b1.x, b1.x); bb[5] = pk2(b1.y, b1.y);
            bb[6] = pk2(b1.z, b1.z); bb[7] = pk2(b1.w, b1.w);
#pragma unroll
            for (int m = 0; m < 4; m++)
#pragma unroll
                for (int j = 0; j < 8; j++)
                    acc[m][j] = fma2(am[m], bb[j], acc[m][j]);
        }
    }

    /* epilogue: add bias, write x_emb (2 rows per m-pair) */
    float4 bv0 = *(const float4*)&bias[d0 + nb];
    float4 bv1 = *(const float4*)&bias[d0 + nb + 4];
    float bvals[8] = {bv0.x,bv0.y,bv0.z,bv0.w,bv1.x,bv1.y,bv1.z,bv1.w};
#pragma unroll
    for (int m = 0; m < 4; m++){
        float lo[8], hi[8];
#pragma unroll
        for (int j = 0; j < 8; j++){
            upk2(acc[m][j], lo[j], hi[j]);
            lo[j] += bvals[j]; hi[j] += bvals[j];
        }
        int gn = n0 + mb + 2*m;
        float* r0 = xemb + gn*DM + d0 + nb;
        float* r1 = r0 + DM;
        *(float4*)r0     = make_float4(lo[0],lo[1],lo[2],lo[3]);
        *(float4*)(r0+4) = make_float4(lo[4],lo[5],lo[6],lo[7]);
        *(float4*)r1     = make_float4(hi[0],hi[1],hi[2],hi[3]);
        *(float4*)(r1+4) = make_float4(hi[4],hi[5],hi[6],hi[7]);
    }
}

/* ---------- x_sq[n] = sum_d x_emb[n,d]^2 (one warp per row) ---------- */
__global__ void xsq_kernel(const float* __restrict__ xemb){
    int w = threadIdx.x >> 5, lane = threadIdx.x & 31;
    int row = blockIdx.x * 8 + w;
    float a = 0.f;
#pragma unroll
    for (int j = 0; j < 4; j++){
        float4 v = *(const float4*)(xemb + row*DM + j*128 + lane*4);
        a += v.x*v.x + v.y*v.y + v.z*v.z + v.w*v.w;
    }
#pragma unroll
    for (int off = 16; off > 0; off >>= 1) a += __shfl_down_sync(0xffffffffu, a, off);
    if (lane == 0) g_xsq[row] = a;
}

/* ---------- one-time c_sq for the initial centroids ---------- */
__global__ void csq_kernel(){
    __shared__ float red[128];
    int k = blockIdx.x, t = threadIdx.x;
    float a = 0.f;
    for (int i = t; i < DM; i += 128){ float v = g_cent[k*DM + i]; a = fmaf(v, v, a); }
    red[t] = a; __syncthreads();
    for (int s = 64; s > 0; s >>= 1){ if (t < s) red[t] += red[t+s]; __syncthreads(); }
    if (t == 0) g_csq[k] = red[0];
}

/* ---------- assign: argmin_k (x_sq - 2 x.c + c_sq), first-index ties ----------
   256 threads = 64 points x 4 centroid-groups of 16. f32x2 over d-pairs. */
__global__ void __launch_bounds__(256) assign_kernel(const float* __restrict__ xemb){
    if (g_done) return;
    __shared__ __align__(16) float xs[64][68];
    __shared__ __align__(16) float cs[64][64];
    __shared__ float bv[4][64];
    __shared__ int   bi[4][64];
    const int tid = threadIdx.x;
    const int pl = tid & 63;
    const int g  = tid >> 6;
    const int p  = blockIdx.x * 64 + pl;

    ull acc2[16];
#pragma unroll
    for (int i = 0; i < 16; i++) acc2[i] = 0ull;

    for (int d0 = 0; d0 < DM; d0 += 64){
#pragma unroll
        for (int j = 0; j < 4; j++){
            int q = j*256 + tid;         /* 0..1023 */
            int r = q >> 4;              /* 0..63   */
            int c4 = (q & 15) * 4;       /* 0..60   */
            float4 v = *(const float4*)(xemb + (blockIdx.x*64 + r)*DM + d0 + c4);
            *(float4*)&xs[r][c4] = v;
            float4 w = *(const float4*)(&g_cent[r*DM + d0 + c4]);
            *(float4*)&cs[r][c4] = w;
        }
        __syncthreads();
#pragma unroll
        for (int dd = 0; dd < 64; dd += 8){
            ulonglong2 X0 = *(const ulonglong2*)&xs[pl][dd];
            ulonglong2 X1 = *(const ulonglong2*)&xs[pl][dd+4];
#pragma unroll
            for (int kk = 0; kk < 16; kk++){
                const float* cp = &cs[g*16 + kk][dd];
                ulonglong2 C0 = *(const ulonglong2*)cp;
                ulonglong2 C1 = *(const ulonglong2*)(cp + 4);
                ull a = acc2[kk];
                a = fma2(X0.x, C0.x, a);
                a = fma2(X0.y, C0.y, a);
                a = fma2(X1.x, C1.x, a);
                a = fma2(X1.y, C1.y, a);
                acc2[kk] = a;
            }
        }
        __syncthreads();
    }

    float xq = g_xsq[p];
    float best = 3.4e38f;
    int bk = 0;
#pragma unroll
    for (int kk = 0; kk < 16; kk++){
        int k = g*16 + kk;
        float lo, hi; upk2(acc2[kk], lo, hi);
        float dot = lo + hi;
        float d2 = (xq - 2.0f*dot) + g_csq[k];
        if (d2 < best){ best = d2; bk = k; }
    }
    bv[g][pl] = best; bi[g][pl] = bk;
    __syncthreads();
    if (g == 0){
#pragma unroll
        for (int gg = 1; gg < 4; gg++){
            float v = bv[gg][pl];
            if (v < best){ best = v; bk = bi[gg][pl]; }
        }
        g_ids[p] = bk;
    }
}

/* ---------- segment-sum partials: grid (4 dim-groups, 64 point-chunks) ----------
   Deterministic: points processed in ascending n within a chunk. */
__global__ void __launch_bounds__(128) partial_kernel(const float* __restrict__ xemb){
    if (g_done) return;
    __shared__ float sums[KC*128];
    __shared__ int sids[128];
    __shared__ int scnt[KC];
    const int tid = threadIdx.x;
    const int dg = blockIdx.x;       /* 0..3  */
    const int ch = blockIdx.y;       /* 0..63 */
    for (int i = tid; i < KC*128; i += 128) sums[i] = 0.f;
    if (tid < KC) scnt[tid] = 0;
    sids[tid] = g_ids[ch*128 + tid];
    __syncthreads();
    const int dbase = dg * 128;
#pragma unroll 4
    for (int p = 0; p < 128; p++){
        int id = sids[p];
        float v = xemb[(ch*128 + p)*DM + dbase + tid];
        sums[id*128 + tid] += v;
        if (dg == 0 && tid == 0) scnt[id]++;
    }
    __syncthreads();
    for (int i = tid; i < KC*128; i += 128){
        int k = i >> 7, dd = i & 127;
        g_part[ch*CENT_SIZE + k*DM + dbase + dd] = sums[i];
    }
    if (dg == 0 && tid < KC) g_pcnt[ch*KC + tid] = scnt[tid];
}

/* ---------- combine: new centroids (in place) + csq + shift + done flag ---------- */
__global__ void __launch_bounds__(512) combine_kernel(int iter){
    if (g_done) return;
    __shared__ float reds[512];
    __shared__ float redc[512];
    const int k = blockIdx.x, d = threadIdx.x;
    float acc = 0.f;
    for (int b = 0; b < NCHUNK; b++) acc += g_part[b*CENT_SIZE + k*DM + d];
    int cnt = 0;
    for (int b = 0; b < NCHUNK; b++) cnt += g_pcnt[b*KC + k];
    float old = g_cent[k*DM + d];
    float nc = (cnt > 0) ? (acc / (float)cnt) : old;
    g_cent[k*DM + d] = nc;
    float df = nc - old;
    reds[d] = df * df;
    redc[d] = nc * nc;
    __syncthreads();
    for (int s = 256; s > 0; s >>= 1){
        if (d < s){ reds[d] += reds[d+s]; redc[d] += redc[d+s]; }
        __syncthreads();
    }
    if (d == 0){ g_shift[k] = reds[0]; g_csq[k] = redc[0]; }
    __threadfence();
    __syncthreads();
    if (d == 0){
        int t = atomicAdd(&g_ctr[iter], 1);
        if (t == KC - 1){
            __threadfence();
            float s = 0.f;
            for (int k2 = 0; k2 < KC; k2++) s += g_shift[k2];
            if (s < 1e-8f) g_done = 1;   /* norm < 1e-4 <=> sumsq < 1e-8 */
        }
    }
}

/* ---------- outputs: one-hot prob + centroid copy ---------- */
__global__ void output_kernel(float* __restrict__ out){
    int i = blockIdx.x * blockDim.x + threadIdx.x;
    if (i < PROB_SIZE){
        out[i] = (g_ids[i >> 6] == (i & 63)) ? 1.0f : 0.0f;
    } else if (i < PROB_SIZE + CENT_SIZE){
        out[i] = g_cent[i - PROB_SIZE];
    }
}

extern "C" void kernel_launch(void* const* d_in, const int* in_sizes, int n_in,
                              void* d_out, int out_size){
    const float* x     = (const float*)d_in[0];   /* [128,2048,64] */
    const float* W     = (const float*)d_in[1];   /* [512,2048]    */
    const float* bias  = (const float*)d_in[2];   /* [512]         */
    const float* cents = (const float*)d_in[3];   /* [64,512]      */
    float* out  = (float*)d_out;
    float* xemb = out + XEMB_OFF;

    init_kernel<<<(CENT_SIZE + 255)/256, 256>>>(cents);
    gemm_kernel<<<dim3(DM/128, NPTS/128), 256>>>(x, W, bias, xemb);
    xsq_kernel<<<NPTS/8, 256>>>(xemb);
    csq_kernel<<<KC, 128>>>();

    for (int it = 0; it < MAX_ITER; it++){
        assign_kernel<<<NPTS/64, 256>>>(xemb);
        partial_kernel<<<dim3(4, NCHUNK), 128>>>(xemb);
        combine_kernel<<<KC, 512>>>(it);
    }
    output_kernel<<<(PROB_SIZE + CENT_SIZE + 255)/256, 256>>>(out);
}